// round 14
// baseline (speedup 1.0000x reference)
#include <cuda_runtime.h>
#include <cuda_bf16.h>
#include <cstdint>

// Persistent 8-CTA-cluster LSTM scan, bf16 m16n8k16 HMMA, 128 SMs,
// gate-pair-split warps (2 mma warps per SMSP), permuted-K local own-h.
// T=2048, B=256, E=128, H=256 (4H=1024 gate rows).
//   16 clusters x 8 CTAs = 128 CTAs (1/SM). Cluster cl: batch [16cl,16cl+16).
//   CTA rank r owns hidden units [32r,32r+32) -> 128 local gate rows = 16 nt.
//   nt = g*4 + ub (gate g 0..3, unit block ub 0..3).
//   Warp w<4 computes gates {0(i),1(f)} for ub=w; warp w>=4 gates {2(g),3(o)}
//   for ub=w-4 -> 2 nt x 24 kt = 48 mma/warp, 96/SMSP (floor ~1536 cyc).
// Permuted per-CTA K layout (24 kt):
//   kt 0..1   : own 32 h cols (local STS)
//   kt 2..15  : peer h cols, peer q=0..6 -> owner (rank+1+q)&7, 2 kt each
//   kt 16..23 : x cols (E=128)
// Step: wait(7-peer mbar) -> post-wait mma 14 peer kt (W in 56 regs) ->
//   upper warps STS g,o gates -> sync -> lower warps cell math (c resident),
//   STS own h, st.async x7 peers; all stage x(t+1) -> sync -> shadow mma
//   (own-h 2kt + x 8kt, W in smem) while pushes fly.

#define T_STEPS 2048
#define BATCH   256
#define EDIM    128
#define HDIM    256
#define CLSZ    8
#define NTHR    256

// smem word map
#define WF_W        0        // smem W frags: 16nt x 10skt x 32 lanes uint2 = 10240 words
#define AF_W        10240    // A fragments: 2 buffers x 3072 words
#define AF_STRIDE_W 3072
#define XG_W        16384    // gate exchange: 8 x 128 floats = 1024 words
#define MB_W        17408    // 2 mbarriers, 8B each
#define SMEM_WORDS  17412    // 69648 bytes

#define AF_BYTE     (AF_W * 4)
#define MB_BYTE     (MB_W * 4)
#define AF_STRIDE_B (AF_STRIDE_W * 4)
#define TX_BYTES    (7 * 128 * 8)   // 7 peer CTAs x 128 pusher threads x 8B = 7168

extern __shared__ uint32_t smem_u[];

__device__ __forceinline__ uint32_t packbf(float lo, float hi) {
    uint32_t u;
    asm("cvt.rn.bf16x2.f32 %0, %1, %2;" : "=r"(u) : "f"(hi), "f"(lo));
    return u;
}
__device__ __forceinline__ float tanha(float x) {
    float y;
    asm("tanh.approx.f32 %0, %1;" : "=f"(y) : "f"(x));
    return y;
}
__device__ __forceinline__ float sigf(float x) { return fmaf(0.5f, tanha(0.5f * x), 0.5f); }
__device__ __forceinline__ void csync() {
    asm volatile("barrier.cluster.arrive.aligned;" ::: "memory");
    asm volatile("barrier.cluster.wait.aligned;" ::: "memory");
}
__device__ __forceinline__ uint32_t smem_u32(const void* p) {
    uint32_t a;
    asm("{ .reg .u64 t; cvta.to.shared.u64 t, %1; cvt.u32.u64 %0, t; }" : "=r"(a) : "l"(p));
    return a;
}
__device__ __forceinline__ uint32_t mapa32(uint32_t a, uint32_t r) {
    uint32_t d;
    asm("mapa.shared::cluster.u32 %0, %1, %2;" : "=r"(d) : "r"(a), "r"(r));
    return d;
}
__device__ __forceinline__ void mbar_init(uint32_t a, uint32_t n) {
    asm volatile("mbarrier.init.shared.b64 [%0], %1;" :: "r"(a), "r"(n) : "memory");
}
__device__ __forceinline__ void mbar_arm(uint32_t a, uint32_t tx) {
    asm volatile("mbarrier.arrive.expect_tx.shared.b64 _, [%0], %1;" :: "r"(a), "r"(tx) : "memory");
}
__device__ __forceinline__ void mbar_wait(uint32_t a, uint32_t phase) {
    uint32_t done;
    asm volatile(
        "{\n\t.reg .pred p;\n\t"
        "mbarrier.try_wait.parity.acquire.cluster.shared::cta.b64 p, [%1], %2;\n\t"
        "selp.b32 %0, 1, 0, p;\n\t}"
        : "=r"(done) : "r"(a), "r"(phase) : "memory");
    if (!done) {
        asm volatile(
            "{\n\t.reg .pred P1;\n\t"
            "W_%=:\n\t"
            "mbarrier.try_wait.parity.acquire.cluster.shared::cta.b64 P1, [%0], %1, 0x989680;\n\t"
            "@P1 bra.uni D_%=;\n\t"
            "bra.uni W_%=;\n\t"
            "D_%=:\n\t}"
            :: "r"(a), "r"(phase) : "memory");
    }
}
__device__ __forceinline__ void st_async64(uint32_t daddr, uint32_t dmbar,
                                           uint32_t lo, uint32_t hi) {
    asm volatile(
        "{\n\t.reg .b64 v;\n\tmov.b64 v, {%2, %3};\n\t"
        "st.async.weak.shared::cluster.mbarrier::complete_tx::bytes.b64 [%0], v, [%1];\n\t}"
        :: "r"(daddr), "r"(dmbar), "r"(lo), "r"(hi) : "memory");
}
__device__ __forceinline__ void mma16816(float d[4], uint32_t a0, uint32_t a1, uint32_t a2,
                                         uint32_t a3, uint32_t b0, uint32_t b1) {
    asm volatile(
        "mma.sync.aligned.m16n8k16.row.col.f32.bf16.bf16.f32 "
        "{%0,%1,%2,%3},{%4,%5,%6,%7},{%8,%9},{%0,%1,%2,%3};"
        : "+f"(d[0]), "+f"(d[1]), "+f"(d[2]), "+f"(d[3])
        : "r"(a0), "r"(a1), "r"(a2), "r"(a3), "r"(b0), "r"(b1));
}
// word offset (within one A buffer) of packed pair holding A[row=b][col,col+1]
// (col is the PERMUTED column index, even)
__device__ __forceinline__ int afrag_word(int b, int col) {
    int kt = col >> 4, kk = col & 15;
    int t3 = (kk >> 1) & 3;
    int r  = ((b >> 3) & 1) | (((kk >> 3) & 1) << 1);
    int ln = (b & 7) * 4 + t3;
    return (kt * 32 + ln) * 4 + r;
}

__global__ void __cluster_dims__(CLSZ, 1, 1) __launch_bounds__(NTHR, 1)
lstm_kernel(const int* __restrict__ inputs, const float* __restrict__ emb,
            const float* __restrict__ Wih, const float* __restrict__ Whh,
            const float* __restrict__ bih, const float* __restrict__ bhh,
            const float* __restrict__ Wout, const float* __restrict__ bout,
            float* __restrict__ out)
{
    const int tid  = threadIdx.x;
    const int lane = tid & 31;
    const int wid  = tid >> 5;
    const int ub   = wid & 3;           // unit block 0..3
    const bool lower = (wid < 4);       // lower: gates i,f + cell math + push
    const int gA   = lower ? 0 : 2;     // first gate of this warp
    const int rank = blockIdx.x & (CLSZ - 1);
    const int cl   = blockIdx.x >> 3;

    uint2*    wf  = (uint2*)(smem_u + WF_W);
    uint32_t* af  = smem_u + AF_W;
    float*    xgb = (float*)(smem_u + XG_W);

    const uint32_t smem_base = smem_u32(smem_u);
    const uint32_t mbL       = smem_base + MB_BYTE;

    // warp's two n-tiles: ntA = gA*4+ub (gate gA), ntB = (gA+1)*4+ub
    const int ntA = gA * 4 + ub;
    const int ntB = ntA + 4;

    // ---- one-time: smem W frags (skt 0..1 own-h, 2..9 x) ----
    for (int idx = tid; idx < 16 * 10 * 32; idx += NTHR) {
        int l   = idx & 31;
        int skt = (idx >> 5) % 10;
        int nt  = idx / (32 * 10);
        int n   = nt * 8 + (l >> 2);
        int R   = ((n >> 5) << 8) + rank * 32 + (n & 31);
        float w00, w01, w10, w11;
        if (skt < 2) {
            int ka = rank * 32 + skt * 16 + (l & 3) * 2;
            w00 = Whh[R * HDIM + ka];     w01 = Whh[R * HDIM + ka + 1];
            w10 = Whh[R * HDIM + ka + 8]; w11 = Whh[R * HDIM + ka + 8 + 1];
        } else {
            int ka = (skt - 2) * 16 + (l & 3) * 2;
            w00 = Wih[R * EDIM + ka];     w01 = Wih[R * EDIM + ka + 1];
            w10 = Wih[R * EDIM + ka + 8]; w11 = Wih[R * EDIM + ka + 8 + 1];
        }
        wf[idx] = make_uint2(packbf(w00, w01), packbf(w10, w11));
    }

    // ---- one-time: PEER h-part W (permuted kt 2..15) -> registers (56 regs) ----
    uint2 wreg[28];
    {
        const int nbase = rank * 32 + ub * 8 + (lane >> 2);
        const int R_A = gA * 256 + nbase;
        const int R_B = (gA + 1) * 256 + nbase;
        #pragma unroll
        for (int k = 0; k < 14; ++k) {
            int o  = (rank + 1 + (k >> 1)) & 7;
            int ka = o * 32 + (k & 1) * 16 + (lane & 3) * 2;
            wreg[k * 2 + 0] =
                make_uint2(packbf(Whh[R_A * HDIM + ka],     Whh[R_A * HDIM + ka + 1]),
                           packbf(Whh[R_A * HDIM + ka + 8], Whh[R_A * HDIM + ka + 8 + 1]));
            wreg[k * 2 + 1] =
                make_uint2(packbf(Whh[R_B * HDIM + ka],     Whh[R_B * HDIM + ka + 1]),
                           packbf(Whh[R_B * HDIM + ka + 8], Whh[R_B * HDIM + ka + 8 + 1]));
        }
    }

    // ---- per-thread cell constants ----
    const int u0 = ub * 8 + ((lane & 3) << 1);
    const int b  = lane >> 2;
    float biasA0, biasA1, biasB0, biasB1;
    {
        int RA = gA * 256 + rank * 32 + u0;
        int RB = (gA + 1) * 256 + rank * 32 + u0;
        biasA0 = bih[RA] + bhh[RA];       biasA1 = bih[RA + 1] + bhh[RA + 1];
        biasB0 = bih[RB] + bhh[RB];       biasB1 = bih[RB + 1] + bhh[RB + 1];
    }
    const int selfWord = afrag_word(b, u0);
    uint32_t peerR[7], peerByte[7];
    {
        int pi = 0;
        #pragma unroll
        for (int r = 0; r < CLSZ; ++r) {
            if (r == rank) continue;
            int q    = (rank - r - 1) & 7;
            int colp = (2 + 2 * q + (u0 >> 4)) * 16 + (u0 & 15);
            peerR[pi]    = mapa32(smem_base, (uint32_t)r);
            peerByte[pi] = (uint32_t)afrag_word(b, colp) * 4;
            ++pi;
        }
    }
    float cst[4] = {0.f, 0.f, 0.f, 0.f};
    const int xgIdx = ub * 32 + lane;   // gate-exchange slot

    // ---- staging constants: thread stages 4 packed x words ----
    const int sb = tid >> 4;
    const int sp = (tid & 15) * 4;
    int sword[4];
    #pragma unroll
    for (int s = 0; s < 4; ++s) sword[s] = afrag_word(sb, 256 + 2 * (sp + s));

    // ---- mbarrier init + prologue ----
    if (tid == 0) {
        mbar_init(mbL + 0, 1);
        mbar_init(mbL + 8, 1);
        mbar_arm(mbL + 8, TX_BYTES);   // gen 1 -> mb1
    }
    for (int w = tid; w < 2 * AF_STRIDE_W; w += NTHR) af[w] = 0u;
    __syncthreads();
    {   // stage x(0) into buf0 (h(0)=0 via zeroing)
        int tok = __ldg(&inputs[cl * 16 + sb]);
        const float4* er = (const float4*)&emb[tok * EDIM + 2 * sp];
        float4 e0 = __ldg(er), e1 = __ldg(er + 1);
        af[sword[0]] = packbf(e0.x, e0.y);
        af[sword[1]] = packbf(e0.z, e0.w);
        af[sword[2]] = packbf(e1.x, e1.y);
        af[sword[3]] = packbf(e1.z, e1.w);
    }
    __syncthreads();
    csync();   // barriers armed + buffers staged cluster-wide before any st.async

    // ---- prime accumulators for step 0: bias + own-h(0)(=0) + x(0) ----
    float accA[4], accB[4];
    accA[0] = biasA0; accA[1] = biasA1; accA[2] = biasA0; accA[3] = biasA1;
    accB[0] = biasB0; accB[1] = biasB1; accB[2] = biasB0; accB[3] = biasB1;
    #pragma unroll
    for (int skt = 0; skt < 10; ++skt) {
        int akt = (skt < 2) ? skt : (16 + skt - 2);
        uint4 a = *(const uint4*)(af + (akt * 32 + lane) * 4);
        uint2 bfA = wf[((ntA * 10 + skt) * 32 + lane)];
        uint2 bfB = wf[((ntB * 10 + skt) * 32 + lane)];
        mma16816(accA, a.x, a.y, a.z, a.w, bfA.x, bfA.y);
        mma16816(accB, a.x, a.y, a.z, a.w, bfB.x, bfB.y);
    }

    uint32_t ph0 = 0, ph1 = 0;

    #define STEP_BODY(T_, PAR_, MBOFF_, PHW_)                                              \
    {                                                                                      \
        const int t = (T_);                                                                \
        const uint32_t mbw = mbL + (MBOFF_);                                               \
        const uint32_t* cur = af + (PAR_) * AF_STRIDE_W;                                   \
        uint32_t*       nxt = af + (1 - (PAR_)) * AF_STRIDE_W;                             \
        const bool more = (t + 1 < T_STEPS);                                               \
        if (t > 0) { mbar_wait(mbw, PHW_); PHW_ ^= 1; }                                    \
        if (tid == 0) mbar_arm(mbw, TX_BYTES);      /* re-arm for gen t+2 */               \
        float4 e0, e1;                                                                     \
        if (more) {                                                                        \
            int tok = __ldg(&inputs[(t + 1) * BATCH + cl * 16 + sb]);                      \
            const float4* er = (const float4*)&emb[tok * EDIM + 2 * sp];                   \
            e0 = __ldg(er); e1 = __ldg(er + 1);                                            \
        }                                                                                  \
        /* post-wait mma: 14 peer kt (permuted kt 2..15), W in registers */                \
        _Pragma("unroll")                                                                  \
        for (int k = 0; k < 14; ++k) {                                                     \
            uint4 a = *(const uint4*)(cur + ((2 + k) * 32 + lane) * 4);                    \
            uint2 bfA = wreg[k * 2 + 0];                                                   \
            uint2 bfB = wreg[k * 2 + 1];                                                   \
            mma16816(accA, a.x, a.y, a.z, a.w, bfA.x, bfA.y);                              \
            mma16816(accB, a.x, a.y, a.z, a.w, bfB.x, bfB.y);                              \
        }                                                                                  \
        /* upper warps publish g,o gates */                                                \
        if (!lower) {                                                                      \
            _Pragma("unroll")                                                              \
            for (int v = 0; v < 4; ++v) {                                                  \
                xgb[v * 128 + xgIdx]       = accA[v];   /* gate g */                       \
                xgb[(4 + v) * 128 + xgIdx] = accB[v];   /* gate o */                       \
            }                                                                              \
        }                                                                                  \
        __syncthreads();                                                                   \
        /* lower warps: cell math + pushes */                                              \
        if (lower) {                                                                       \
            float gg0 = tanha(xgb[0 * 128 + xgIdx]);                                       \
            float gg1 = tanha(xgb[1 * 128 + xgIdx]);                                       \
            float gg2 = tanha(xgb[2 * 128 + xgIdx]);                                       \
            float gg3 = tanha(xgb[3 * 128 + xgIdx]);                                       \
            float oo0 = sigf(xgb[4 * 128 + xgIdx]);                                        \
            float oo1 = sigf(xgb[5 * 128 + xgIdx]);                                        \
            float oo2 = sigf(xgb[6 * 128 + xgIdx]);                                        \
            float oo3 = sigf(xgb[7 * 128 + xgIdx]);                                        \
            float i0 = sigf(accA[0]), i1 = sigf(accA[1]), i2 = sigf(accA[2]), i3 = sigf(accA[3]); \
            float f0 = sigf(accB[0]), f1 = sigf(accB[1]), f2 = sigf(accB[2]), f3 = sigf(accB[3]); \
            cst[0] = f0 * cst[0] + i0 * gg0;                                               \
            cst[1] = f1 * cst[1] + i1 * gg1;                                               \
            cst[2] = f2 * cst[2] + i2 * gg2;                                               \
            cst[3] = f3 * cst[3] + i3 * gg3;                                               \
            uint32_t hw0 = packbf(oo0 * tanha(cst[0]), oo1 * tanha(cst[1]));               \
            uint32_t hw1 = packbf(oo2 * tanha(cst[2]), oo3 * tanha(cst[3]));               \
            nxt[selfWord]     = hw0;                                                       \
            nxt[selfWord + 1] = hw1;                                                       \
            const uint32_t afoff = AF_BYTE + (1 - (PAR_)) * AF_STRIDE_B;                   \
            const uint32_t mboff = MB_BYTE + (8 - (MBOFF_));                               \
            _Pragma("unroll")                                                              \
            for (int p = 0; p < 7; ++p)                                                    \
                st_async64(peerR[p] + afoff + peerByte[p], peerR[p] + mboff, hw0, hw1);    \
        }                                                                                  \
        /* all: stage x(t+1) locally */                                                    \
        if (more) {                                                                        \
            nxt[sword[0]] = packbf(e0.x, e0.y);                                            \
            nxt[sword[1]] = packbf(e0.z, e0.w);                                            \
            nxt[sword[2]] = packbf(e1.x, e1.y);                                            \
            nxt[sword[3]] = packbf(e1.z, e1.w);                                            \
        }                                                                                  \
        __syncthreads();   /* own-h(t+1) + x(t+1) staged before shadow mma */              \
        /* SHADOW: re-init accs for t+1, local data only (runs while pushes fly) */        \
        accA[0] = biasA0; accA[1] = biasA1; accA[2] = biasA0; accA[3] = biasA1;            \
        accB[0] = biasB0; accB[1] = biasB1; accB[2] = biasB0; accB[3] = biasB1;            \
        {   /* own-h kt 0..1 always valid */                                               \
            _Pragma("unroll")                                                              \
            for (int skt = 0; skt < 2; ++skt) {                                            \
                uint4 a = *(const uint4*)(nxt + (skt * 32 + lane) * 4);                    \
                uint2 bfA = wf[((ntA * 10 + skt) * 32 + lane)];                            \
                uint2 bfB = wf[((ntB * 10 + skt) * 32 + lane)];                            \
                mma16816(accA, a.x, a.y, a.z, a.w, bfA.x, bfA.y);                          \
                mma16816(accB, a.x, a.y, a.z, a.w, bfB.x, bfB.y);                          \
            }                                                                              \
        }                                                                                  \
        if (more) {                                                                        \
            _Pragma("unroll")                                                              \
            for (int skt = 2; skt < 10; ++skt) {                                           \
                uint4 a = *(const uint4*)(nxt + ((16 + skt - 2) * 32 + lane) * 4);         \
                uint2 bfA = wf[((ntA * 10 + skt) * 32 + lane)];                            \
                uint2 bfB = wf[((ntB * 10 + skt) * 32 + lane)];                            \
                mma16816(accA, a.x, a.y, a.z, a.w, bfA.x, bfA.y);                          \
                mma16816(accB, a.x, a.y, a.z, a.w, bfB.x, bfB.y);                          \
            }                                                                              \
        }                                                                                  \
    }

    for (int tt = 0; tt < T_STEPS; tt += 2) {
        STEP_BODY(tt,     0, 0, ph0)   // even: wait mb0, push -> mb1
        STEP_BODY(tt + 1, 1, 8, ph1)   // odd:  wait mb1, push -> mb0
    }
    #undef STEP_BODY

    // final: gen 2048 (parity at mb0) must land everywhere before reads/exit
    mbar_wait(mbL + 0, ph0);

    // ---- head: h_T in buffer 0, rank-0's permuted layout ----
    if (rank == 0 && tid < 16) {
        float s = __ldg(bout);
        int bb = tid;
        float accv = 0.0f;
        #pragma unroll 8
        for (int j = 0; j < HDIM; j += 2) {
            int o = j >> 5, w = j & 31;
            int kt = (o == 0) ? (w >> 4) : (2 + 2 * (o - 1) + (w >> 4));
            int colp = kt * 16 + (w & 15);
            uint32_t u = af[afrag_word(bb, colp)];
            float lo = __uint_as_float(u << 16);
            float hi = __uint_as_float(u & 0xFFFF0000u);
            accv += lo * __ldg(&Wout[j]) + hi * __ldg(&Wout[j + 1]);
        }
        out[cl * 16 + bb] = sigf(s + accv);
    }

    // keep cluster alive until all CTAs have received their final pushes
    csync();
}

extern "C" void kernel_launch(void* const* d_in, const int* in_sizes, int n_in,
                              void* d_out, int out_size)
{
    (void)in_sizes; (void)n_in; (void)out_size;
    cudaFuncSetAttribute(lstm_kernel, cudaFuncAttributeMaxDynamicSharedMemorySize,
                         SMEM_WORDS * 4);
    lstm_kernel<<<16 * CLSZ, NTHR, SMEM_WORDS * 4>>>(
        (const int*)d_in[0], (const float*)d_in[1], (const float*)d_in[2],
        (const float*)d_in[3], (const float*)d_in[4], (const float*)d_in[5],
        (const float*)d_in[6], (const float*)d_in[7], (float*)d_out);
}

// round 15
// speedup vs baseline: 2.0010x; 2.0010x over previous
#include <cuda_runtime.h>
#include <cuda_bf16.h>
#include <cstdint>

// Persistent 4-CTA-cluster LSTM scan, bf16 m16n8k16 HMMA, permuted-K layout,
// BULK DSMEM h exchange: one cp.async.bulk (2048 B) per peer per step instead
// of 256 st.async messages (message-rate was the dominant per-step cost).
// T=2048, B=256, E=128, H=256. 16 clusters x 4 CTAs = 64 CTAs.
// CTA rank r owns hidden units [64r,64r+64) -> 256 local gate rows.
// Per-CTA A/W column order (24 k16-tiles):
//   kt 0..3   : own h columns  (STS after cell math; also the bulk-copy SOURCE)
//   kt 4..15  : peer h cols, peer q=0..2 -> owner (rank+1+q)&4.., 4 kt each
//               (arrive via cp.async.bulk from peers; parity mbarrier counts
//                3 x 2048 tx bytes per generation)
//   kt 16..23 : x columns (staged locally from emb)
// Step: wait(mbar) -> peer-h mma kt4..15 (W in 96 regs) -> cell math (c in
//   regs) -> STS own h -> stage x(t+1) -> __syncthreads -> tid0:
//   fence.proxy.async + 3x cp.async.bulk own-block -> peers' q-block /
//   peer barrier -> SHADOW mma for t+1 (own-h + x, W in smem) while copies fly.

#define T_STEPS 2048
#define BATCH   256
#define EDIM    128
#define HDIM    256
#define CLSZ    4
#define NTHR    256

// smem word map
#define WF_W        0        // smem W frags: 32nt x 12skt x 32 lanes uint2 = 24576 words
#define AF_W        24576    // A fragments: 2 buffers x 3072 words
#define AF_STRIDE_W 3072
#define MB_W        30720    // 2 mbarriers, 8B each
#define SMEM_WORDS  30728    // 122912 bytes

#define AF_BYTE     (AF_W * 4)
#define MB_BYTE     (MB_W * 4)
#define AF_STRIDE_B (AF_STRIDE_W * 4)
#define OWN_BLK_B   2048                 // kt 0..3 = 4 kt x 512 B
#define TX_BYTES    (3 * OWN_BLK_B)      // 3 peers x 2048 B = 6144

extern __shared__ uint32_t smem_u[];

__device__ __forceinline__ uint32_t packbf(float lo, float hi) {
    uint32_t u;
    asm("cvt.rn.bf16x2.f32 %0, %1, %2;" : "=r"(u) : "f"(hi), "f"(lo));
    return u;
}
__device__ __forceinline__ float tanha(float x) {
    float y;
    asm("tanh.approx.f32 %0, %1;" : "=f"(y) : "f"(x));
    return y;
}
__device__ __forceinline__ float sigf(float x) { return fmaf(0.5f, tanha(0.5f * x), 0.5f); }
__device__ __forceinline__ void csync() {
    asm volatile("barrier.cluster.arrive.aligned;" ::: "memory");
    asm volatile("barrier.cluster.wait.aligned;" ::: "memory");
}
__device__ __forceinline__ uint32_t smem_u32(const void* p) {
    uint32_t a;
    asm("{ .reg .u64 t; cvta.to.shared.u64 t, %1; cvt.u32.u64 %0, t; }" : "=r"(a) : "l"(p));
    return a;
}
__device__ __forceinline__ uint32_t mapa32(uint32_t a, uint32_t r) {
    uint32_t d;
    asm("mapa.shared::cluster.u32 %0, %1, %2;" : "=r"(d) : "r"(a), "r"(r));
    return d;
}
__device__ __forceinline__ void mbar_init(uint32_t a, uint32_t n) {
    asm volatile("mbarrier.init.shared.b64 [%0], %1;" :: "r"(a), "r"(n) : "memory");
}
__device__ __forceinline__ void mbar_arm(uint32_t a, uint32_t tx) {
    asm volatile("mbarrier.arrive.expect_tx.shared.b64 _, [%0], %1;" :: "r"(a), "r"(tx) : "memory");
}
__device__ __forceinline__ void mbar_wait(uint32_t a, uint32_t phase) {
    uint32_t done;
    asm volatile(
        "{\n\t.reg .pred p;\n\t"
        "mbarrier.try_wait.parity.acquire.cluster.shared::cta.b64 p, [%1], %2;\n\t"
        "selp.b32 %0, 1, 0, p;\n\t}"
        : "=r"(done) : "r"(a), "r"(phase) : "memory");
    if (!done) {
        asm volatile(
            "{\n\t.reg .pred P1;\n\t"
            "W_%=:\n\t"
            "mbarrier.try_wait.parity.acquire.cluster.shared::cta.b64 P1, [%0], %1, 0x989680;\n\t"
            "@P1 bra.uni D_%=;\n\t"
            "bra.uni W_%=;\n\t"
            "D_%=:\n\t}"
            :: "r"(a), "r"(phase) : "memory");
    }
}
// Bulk DSMEM copy: local smem block -> peer CTA smem, tx-completion at the
// (peer's) mbarrier. All addresses are shared-window addresses.
__device__ __forceinline__ void bulk_s2s(uint32_t dst, uint32_t src, uint32_t bytes,
                                         uint32_t mbar) {
    asm volatile(
        "cp.async.bulk.shared::cluster.shared::cta.mbarrier::complete_tx::bytes "
        "[%0], [%1], %2, [%3];"
        :: "r"(dst), "r"(src), "r"(bytes), "r"(mbar) : "memory");
}
__device__ __forceinline__ void fence_proxy_async_cta() {
    asm volatile("fence.proxy.async.shared::cta;" ::: "memory");
}
__device__ __forceinline__ void mma16816(float d[4], uint32_t a0, uint32_t a1, uint32_t a2,
                                         uint32_t a3, uint32_t b0, uint32_t b1) {
    asm volatile(
        "mma.sync.aligned.m16n8k16.row.col.f32.bf16.bf16.f32 "
        "{%0,%1,%2,%3},{%4,%5,%6,%7},{%8,%9},{%0,%1,%2,%3};"
        : "+f"(d[0]), "+f"(d[1]), "+f"(d[2]), "+f"(d[3])
        : "r"(a0), "r"(a1), "r"(a2), "r"(a3), "r"(b0), "r"(b1));
}
// word offset (within one A buffer) of packed pair holding A[row=b][col,col+1]
// (col is the PERMUTED column index, even)
__device__ __forceinline__ int afrag_word(int b, int col) {
    int kt = col >> 4, kk = col & 15;
    int t3 = (kk >> 1) & 3;
    int r  = ((b >> 3) & 1) | (((kk >> 3) & 1) << 1);
    int ln = (b & 7) * 4 + t3;
    return (kt * 32 + ln) * 4 + r;
}

__global__ void __cluster_dims__(CLSZ, 1, 1) __launch_bounds__(NTHR, 1)
lstm_kernel(const int* __restrict__ inputs, const float* __restrict__ emb,
            const float* __restrict__ Wih, const float* __restrict__ Whh,
            const float* __restrict__ bih, const float* __restrict__ bhh,
            const float* __restrict__ Wout, const float* __restrict__ bout,
            float* __restrict__ out)
{
    const int tid  = threadIdx.x;
    const int lane = tid & 31;
    const int wid  = tid >> 5;
    const int rank = blockIdx.x & (CLSZ - 1);
    const int cl   = blockIdx.x >> 2;

    uint2*    wf = (uint2*)(smem_u + WF_W);
    uint32_t* af = smem_u + AF_W;

    const uint32_t smem_base = smem_u32(smem_u);
    const uint32_t mbL       = smem_base + MB_BYTE;

    // ---- one-time: smem W frags (skt 0..3 own-h, 4..11 x) ----
    for (int idx = tid; idx < 32 * 12 * 32; idx += NTHR) {
        int l   = idx & 31;
        int skt = (idx >> 5) % 12;
        int nt  = idx / (32 * 12);
        int n   = nt * 8 + (l >> 2);
        int R   = ((n >> 6) << 8) + rank * 64 + (n & 63);
        float w00, w01, w10, w11;
        if (skt < 4) {
            int ka = rank * 64 + skt * 16 + (l & 3) * 2;
            w00 = Whh[R * HDIM + ka];     w01 = Whh[R * HDIM + ka + 1];
            w10 = Whh[R * HDIM + ka + 8]; w11 = Whh[R * HDIM + ka + 8 + 1];
        } else {
            int ka = (skt - 4) * 16 + (l & 3) * 2;
            w00 = Wih[R * EDIM + ka];     w01 = Wih[R * EDIM + ka + 1];
            w10 = Wih[R * EDIM + ka + 8]; w11 = Wih[R * EDIM + ka + 8 + 1];
        }
        wf[idx] = make_uint2(packbf(w00, w01), packbf(w10, w11));
    }

    // ---- one-time: PEER h-part W (permuted kt 4..15) -> registers (96 regs) ----
    uint2 wreg[48];
    {
        const int nbase = rank * 64 + wid * 8 + (lane >> 2);
        #pragma unroll
        for (int k = 0; k < 12; ++k) {
            int o  = (rank + 1 + (k >> 2)) & 3;
            int ka = o * 64 + (k & 3) * 16 + (lane & 3) * 2;
            #pragma unroll
            for (int g = 0; g < 4; ++g) {
                int R = (g << 8) + nbase;
                wreg[k * 4 + g] =
                    make_uint2(packbf(Whh[R * HDIM + ka],     Whh[R * HDIM + ka + 1]),
                               packbf(Whh[R * HDIM + ka + 8], Whh[R * HDIM + ka + 8 + 1]));
            }
        }
    }

    // ---- per-thread cell constants ----
    const int u0 = 8 * wid + ((lane & 3) << 1);
    const int b  = lane >> 2;
    float bias0[4], bias1[4];
    #pragma unroll
    for (int g = 0; g < 4; ++g) {
        int R0 = (g << 8) + rank * 64 + u0;
        bias0[g] = bih[R0] + bhh[R0];
        bias1[g] = bih[R0 + 1] + bhh[R0 + 1];
    }
    const int selfWord = afrag_word(b, u0);   // local STS target in own block
    float cst[4] = {0.f, 0.f, 0.f, 0.f};

    // bulk-exchange targets (uniform; used by tid 0)
    //   peer r receives our block at its q-block: q = (rank - r - 1) & 3,
    //   dest byte offset within their A buffer = (4 + 4q) * 512
    uint32_t dstAF[3], dstMB[3];
    {
        int pi = 0;
        #pragma unroll
        for (int r = 0; r < CLSZ; ++r) {
            if (r == rank) continue;
            int q       = (rank - r - 1) & 3;
            uint32_t pb = mapa32(smem_base, (uint32_t)r);
            dstAF[pi]   = pb + AF_BYTE + (uint32_t)(4 + 4 * q) * 512u;
            dstMB[pi]   = pb + MB_BYTE;
            ++pi;
        }
    }

    // ---- staging constants: thread stages 4 packed x words (one batch row) ----
    const int sb = tid >> 4;
    const int sp = (tid & 15) * 4;
    int sword[4];
    #pragma unroll
    for (int s = 0; s < 4; ++s) sword[s] = afrag_word(sb, 256 + 2 * (sp + s));

    // ---- mbarrier init + prologue ----
    if (tid == 0) {
        mbar_init(mbL + 0, 1);
        mbar_init(mbL + 8, 1);
        mbar_arm(mbL + 8, TX_BYTES);   // gen 1 -> mb1
    }
    for (int w = tid; w < 2 * AF_STRIDE_W; w += NTHR) af[w] = 0u;
    __syncthreads();
    {   // stage x(0) into buf0 (own/peer h(0) = 0 via zeroing)
        int tok = __ldg(&inputs[cl * 16 + sb]);
        const float4* er = (const float4*)&emb[tok * EDIM + 2 * sp];
        float4 e0 = __ldg(er), e1 = __ldg(er + 1);
        af[sword[0]] = packbf(e0.x, e0.y);
        af[sword[1]] = packbf(e0.z, e0.w);
        af[sword[2]] = packbf(e1.x, e1.y);
        af[sword[3]] = packbf(e1.z, e1.w);
    }
    __syncthreads();
    csync();   // barriers armed + buffers staged cluster-wide before any bulk copy

    // ---- prime shadow accumulators for step 0: bias + own-h(0)(=0) + x(0) ----
    float accA[4][4], accB[4][4];
    #pragma unroll
    for (int g = 0; g < 4; ++g) {
        accA[g][0] = bias0[g]; accA[g][1] = bias1[g];
        accA[g][2] = bias0[g]; accA[g][3] = bias1[g];
        accB[g][0] = 0.f; accB[g][1] = 0.f; accB[g][2] = 0.f; accB[g][3] = 0.f;
    }
    #pragma unroll
    for (int skt = 0; skt < 12; ++skt) {
        int akt = (skt < 4) ? skt : (16 + skt - 4);
        uint4 a = *(const uint4*)(af + (akt * 32 + lane) * 4);
        #pragma unroll
        for (int g = 0; g < 4; ++g) {
            uint2 bf = wf[((wid + 8 * g) * 12 + skt) * 32 + lane];
            if (skt < 6) mma16816(accA[g], a.x, a.y, a.z, a.w, bf.x, bf.y);
            else         mma16816(accB[g], a.x, a.y, a.z, a.w, bf.x, bf.y);
        }
    }

    uint32_t ph0 = 0, ph1 = 0;

    #define STEP_BODY(T_, PAR_, MBOFF_, PHW_)                                              \
    {                                                                                      \
        const int t = (T_);                                                                \
        const uint32_t mbw = mbL + (MBOFF_);                                               \
        const uint32_t* cur = af + (PAR_) * AF_STRIDE_W;                                   \
        uint32_t*       nxt = af + (1 - (PAR_)) * AF_STRIDE_W;                             \
        const bool more = (t + 1 < T_STEPS);                                               \
        if (t > 0) { mbar_wait(mbw, PHW_); PHW_ ^= 1; }                                    \
        if (tid == 0) mbar_arm(mbw, TX_BYTES);      /* re-arm for gen t+2 */               \
        /* emb loads for x(t+1) issued early */                                            \
        float4 e0, e1;                                                                     \
        if (more) {                                                                        \
            int tok = __ldg(&inputs[(t + 1) * BATCH + cl * 16 + sb]);                      \
            const float4* er = (const float4*)&emb[tok * EDIM + 2 * sp];                   \
            e0 = __ldg(er); e1 = __ldg(er + 1);                                            \
        }                                                                                  \
        /* peer-h mma: permuted kt 4..15, W from registers; split chains */                \
        _Pragma("unroll")                                                                  \
        for (int k = 0; k < 6; ++k) {                                                      \
            uint4 a = *(const uint4*)(cur + ((4 + k) * 32 + lane) * 4);                    \
            _Pragma("unroll")                                                              \
            for (int g = 0; g < 4; ++g) {                                                  \
                uint2 bf = wreg[k * 4 + g];                                                \
                mma16816(accA[g], a.x, a.y, a.z, a.w, bf.x, bf.y);                         \
            }                                                                              \
        }                                                                                  \
        _Pragma("unroll")                                                                  \
        for (int k = 6; k < 12; ++k) {                                                     \
            uint4 a = *(const uint4*)(cur + ((4 + k) * 32 + lane) * 4);                    \
            _Pragma("unroll")                                                              \
            for (int g = 0; g < 4; ++g) {                                                  \
                uint2 bf = wreg[k * 4 + g];                                                \
                mma16816(accB[g], a.x, a.y, a.z, a.w, bf.x, bf.y);                         \
            }                                                                              \
        }                                                                                  \
        /* cell update in registers */                                                     \
        float s0[4], s1[4], s2[4], s3[4];                                                  \
        _Pragma("unroll")                                                                  \
        for (int g = 0; g < 4; ++g) {                                                      \
            s0[g] = accA[g][0] + accB[g][0];                                               \
            s1[g] = accA[g][1] + accB[g][1];                                               \
            s2[g] = accA[g][2] + accB[g][2];                                               \
            s3[g] = accA[g][3] + accB[g][3];                                               \
        }                                                                                  \
        float i0 = sigf(s0[0]), i1 = sigf(s1[0]), i2 = sigf(s2[0]), i3 = sigf(s3[0]);      \
        float f0 = sigf(s0[1]), f1 = sigf(s1[1]), f2 = sigf(s2[1]), f3 = sigf(s3[1]);      \
        float g0 = tanha(s0[2]), g1 = tanha(s1[2]), g2 = tanha(s2[2]), g3 = tanha(s3[2]);  \
        float o0 = sigf(s0[3]), o1 = sigf(s1[3]), o2 = sigf(s2[3]), o3 = sigf(s3[3]);      \
        cst[0] = f0 * cst[0] + i0 * g0;                                                    \
        cst[1] = f1 * cst[1] + i1 * g1;                                                    \
        cst[2] = f2 * cst[2] + i2 * g2;                                                    \
        cst[3] = f3 * cst[3] + i3 * g3;                                                    \
        uint32_t hw0 = packbf(o0 * tanha(cst[0]), o1 * tanha(cst[1]));                     \
        uint32_t hw1 = packbf(o2 * tanha(cst[2]), o3 * tanha(cst[3]));                     \
        /* own h -> local STS into own block of nxt */                                     \
        nxt[selfWord]     = hw0;                                                           \
        nxt[selfWord + 1] = hw1;                                                           \
        /* stage x(t+1) locally */                                                         \
        if (more) {                                                                        \
            nxt[sword[0]] = packbf(e0.x, e0.y);                                            \
            nxt[sword[1]] = packbf(e0.z, e0.w);                                            \
            nxt[sword[2]] = packbf(e1.x, e1.y);                                            \
            nxt[sword[3]] = packbf(e1.z, e1.w);                                            \
        }                                                                                  \
        __syncthreads();   /* own-h(t+1) + x(t+1) complete before copy/shadow */           \
        /* BULK exchange: own 2048-B block -> each peer's q-block, tx at peer barrier */   \
        if (tid == 0) {                                                                    \
            fence_proxy_async_cta();                                                       \
            uint32_t srcB  = smem_base + AF_BYTE + (1 - (PAR_)) * AF_STRIDE_B;             \
            uint32_t dOff  = (uint32_t)((1 - (PAR_)) * AF_STRIDE_B);                       \
            uint32_t mOff  = (uint32_t)(8 - (MBOFF_));                                     \
            bulk_s2s(dstAF[0] + dOff, srcB, OWN_BLK_B, dstMB[0] + mOff);                   \
            bulk_s2s(dstAF[1] + dOff, srcB, OWN_BLK_B, dstMB[1] + mOff);                   \
            bulk_s2s(dstAF[2] + dOff, srcB, OWN_BLK_B, dstMB[2] + mOff);                   \
        }                                                                                  \
        /* SHADOW: accumulators for t+1 from purely local data (runs while copies fly) */  \
        _Pragma("unroll")                                                                  \
        for (int g = 0; g < 4; ++g) {                                                      \
            accA[g][0] = bias0[g]; accA[g][1] = bias1[g];                                  \
            accA[g][2] = bias0[g]; accA[g][3] = bias1[g];                                  \
            accB[g][0] = 0.f; accB[g][1] = 0.f; accB[g][2] = 0.f; accB[g][3] = 0.f;        \
        }                                                                                  \
        _Pragma("unroll")                                                                  \
        for (int skt = 0; skt < 4; ++skt) {   /* own-h kt 0..3 (always valid) */           \
            uint4 a = *(const uint4*)(nxt + (skt * 32 + lane) * 4);                        \
            _Pragma("unroll")                                                              \
            for (int g = 0; g < 4; ++g) {                                                  \
                uint2 bf = wf[((wid + 8 * g) * 12 + skt) * 32 + lane];                     \
                mma16816(accA[g], a.x, a.y, a.z, a.w, bf.x, bf.y);                         \
            }                                                                              \
        }                                                                                  \
        if (more) {                           /* x kt 16..23 */                            \
            _Pragma("unroll")                                                              \
            for (int skt = 4; skt < 12; ++skt) {                                           \
                uint4 a = *(const uint4*)(nxt + ((16 + skt - 4) * 32 + lane) * 4);         \
                _Pragma("unroll")                                                          \
                for (int g = 0; g < 4; ++g) {                                              \
                    uint2 bf = wf[((wid + 8 * g) * 12 + skt) * 32 + lane];                 \
                    if (skt < 8) mma16816(accA[g], a.x, a.y, a.z, a.w, bf.x, bf.y);        \
                    else         mma16816(accB[g], a.x, a.y, a.z, a.w, bf.x, bf.y);        \
                }                                                                          \
            }                                                                              \
        }                                                                                  \
    }

    for (int tt = 0; tt < T_STEPS; tt += 2) {
        STEP_BODY(tt,     0, 0, ph0)   // even: wait mb0, copies signal peers' mb1
        STEP_BODY(tt + 1, 1, 8, ph1)   // odd:  wait mb1, copies signal peers' mb0
    }
    #undef STEP_BODY

    // final: gen 2048 (parity at mb0) must land in every CTA before reads/exit
    mbar_wait(mbL + 0, ph0);

    // ---- head: h_T in buffer 0, PERMUTED fragment layout (rank 0's view) ----
    if (rank == 0 && tid < 16) {
        float s = __ldg(bout);
        int bb = tid;
        float accv = 0.0f;
        #pragma unroll 8
        for (int j = 0; j < HDIM; j += 2) {
            int o = j >> 6, w = j & 63;
            int kt = (o == 0) ? (w >> 4) : (4 + (o - 1) * 4 + (w >> 4));
            int colp = kt * 16 + (w & 15);
            uint32_t u = af[afrag_word(bb, colp)];
            float lo = __uint_as_float(u << 16);
            float hi = __uint_as_float(u & 0xFFFF0000u);
            accv += lo * __ldg(&Wout[j]) + hi * __ldg(&Wout[j + 1]);
        }
        out[cl * 16 + bb] = sigf(s + accv);
    }

    // keep cluster alive until all CTAs have received their final copies
    csync();
}

extern "C" void kernel_launch(void* const* d_in, const int* in_sizes, int n_in,
                              void* d_out, int out_size)
{
    (void)in_sizes; (void)n_in; (void)out_size;
    cudaFuncSetAttribute(lstm_kernel, cudaFuncAttributeMaxDynamicSharedMemorySize,
                         SMEM_WORDS * 4);
    lstm_kernel<<<16 * CLSZ, NTHR, SMEM_WORDS * 4>>>(
        (const int*)d_in[0], (const float*)d_in[1], (const float*)d_in[2],
        (const float*)d_in[3], (const float*)d_in[4], (const float*)d_in[5],
        (const float*)d_in[6], (const float*)d_in[7], (float*)d_out);
}